// round 6
// baseline (speedup 1.0000x reference)
#include <cuda_runtime.h>
#include <cuda_bf16.h>
#include <math.h>

#define GRAVITY_C 9.81f
#define W_INERTIA 1.0f
#define W_GRAVITY 0.01f
#define W_STRAIN  1.0f

#define BLK 256

__device__ double g_acc = 0.0;
__device__ unsigned int g_count = 0;

// -------- block reduction helper (double) --------
__device__ __forceinline__ double block_reduce(double v) {
    #pragma unroll
    for (int off = 16; off > 0; off >>= 1)
        v += __shfl_down_sync(0xFFFFFFFFu, v, off);
    __shared__ double sh[32];
    int lane = threadIdx.x & 31;
    int wid  = threadIdx.x >> 5;
    if (lane == 0) sh[wid] = v;
    __syncthreads();
    int nwarps = (blockDim.x + 31) >> 5;
    v = (threadIdx.x < nwarps) ? sh[threadIdx.x] : 0.0;
    if (wid == 0) {
        #pragma unroll
        for (int off = 16; off > 0; off >>= 1)
            v += __shfl_down_sync(0xFFFFFFFFu, v, off);
    }
    return v;
}

// Per-element Neo-Hookean energy contribution (psi * vol)
__device__ __forceinline__ float elem_energy(const float* __restrict__ pos_next,
                                             const int4 idx,
                                             const float* __restrict__ R,
                                             float vol, float lam, float mu) {
    const int i0 = idx.x, i1 = idx.y, i2 = idx.z, i3 = idx.w;
    float v0x = pos_next[3*i0+0], v0y = pos_next[3*i0+1], v0z = pos_next[3*i0+2];
    float v1x = pos_next[3*i1+0], v1y = pos_next[3*i1+1], v1z = pos_next[3*i1+2];
    float v2x = pos_next[3*i2+0], v2y = pos_next[3*i2+1], v2z = pos_next[3*i2+2];
    float v3x = pos_next[3*i3+0], v3y = pos_next[3*i3+1], v3z = pos_next[3*i3+2];

    float d00 = v1x - v0x, d01 = v2x - v0x, d02 = v3x - v0x;
    float d10 = v1y - v0y, d11 = v2y - v0y, d12 = v3y - v0y;
    float d20 = v1z - v0z, d21 = v2z - v0z, d22 = v3z - v0z;

    float r00 = R[0], r01 = R[1], r02 = R[2];
    float r10 = R[3], r11 = R[4], r12 = R[5];
    float r20 = R[6], r21 = R[7], r22 = R[8];

    float f00 = d00*r00 + d01*r10 + d02*r20;
    float f01 = d00*r01 + d01*r11 + d02*r21;
    float f02 = d00*r02 + d01*r12 + d02*r22;
    float f10 = d10*r00 + d11*r10 + d12*r20;
    float f11 = d10*r01 + d11*r11 + d12*r21;
    float f12 = d10*r02 + d11*r12 + d12*r22;
    float f20 = d20*r00 + d21*r10 + d22*r20;
    float f21 = d20*r01 + d21*r11 + d22*r21;
    float f22 = d20*r02 + d21*r12 + d22*r22;

    float det = f00 * (f11*f22 - f12*f21)
              - f01 * (f10*f22 - f12*f20)
              + f02 * (f10*f21 - f11*f20);
    det = fmaxf(det, 1e-8f);
    float logd = logf(det);

    float tr = f00*f00 + f01*f01 + f02*f02
             + f10*f10 + f11*f11 + f12*f12
             + f20*f20 + f21*f21 + f22*f22;

    float psi = 0.5f * lam * logd * logd - mu * logd + 0.5f * mu * (tr - 3.0f);
    return psi * vol;
}

__global__ void __launch_bounds__(BLK)
fused_kernel(const float* __restrict__ pos_next,
             const float* __restrict__ pos_curr,
             const float* __restrict__ pos_prev,
             const float* __restrict__ mass,
             const int*   __restrict__ elements,
             const float* __restrict__ rest_volumes,
             const float* __restrict__ rest_inv,
             const float* __restrict__ lam_p,
             const float* __restrict__ mu_p,
             int V, int E,
             float* __restrict__ out) {
    const int tid = blockIdx.x * BLK + threadIdx.x;
    const int T   = gridDim.x * BLK;

    double local = 0.0;

    // ---- vertex part: inertia + gravity (grid-stride) ----
    {
        const double inv3V = 1.0 / (3.0 * (double)V);
        const double invV  = 1.0 / (double)V;
        for (int v = tid; v < V; v += T) {
            float m  = mass[v];
            float nx = pos_next[3*v+0], ny = pos_next[3*v+1], nz = pos_next[3*v+2];
            float cx = pos_curr[3*v+0], cy = pos_curr[3*v+1], cz = pos_curr[3*v+2];
            float px = pos_prev[3*v+0], py = pos_prev[3*v+1], pz = pos_prev[3*v+2];
            float ax = nx + px - 2.0f * cx;
            float ay = ny + py - 2.0f * cy;
            float az = nz + pz - 2.0f * cz;
            float a2 = ax*ax + ay*ay + az*az;
            local += (double)(0.5f * m * a2) * (W_INERTIA * inv3V)
                   - (double)(m * GRAVITY_C * cy) * (W_GRAVITY * invV);
        }
    }

    // ---- element part: 2 elements per thread for doubled memory-level parallelism ----
    {
        const float lam = lam_p[0];
        const float mu  = mu_p[0];
        const double invE = 1.0 / (double)E;
        const int H = (E + 1) >> 1;
        const int4* __restrict__ elem4 = reinterpret_cast<const int4*>(elements);

        for (int e0 = tid; e0 < H; e0 += T) {
            const int e1 = e0 + H;
            // issue both index loads + both rest_inv bases up front
            int4 idxA = elem4[e0];
            float volA = rest_volumes[e0];
            const float* RA = rest_inv + (size_t)e0 * 9;

            if (e1 < E) {
                int4 idxB = elem4[e1];
                float volB = rest_volumes[e1];
                const float* RB = rest_inv + (size_t)e1 * 9;
                float cA = elem_energy(pos_next, idxA, RA, volA, lam, mu);
                float cB = elem_energy(pos_next, idxB, RB, volB, lam, mu);
                local += (double)(cA + cB) * (W_STRAIN * invE);
            } else {
                float cA = elem_energy(pos_next, idxA, RA, volA, lam, mu);
                local += (double)cA * (W_STRAIN * invE);
            }
        }
    }

    // ---- reduction + completion-counter epilogue ----
    double bsum = block_reduce(local);
    if (threadIdx.x == 0) {
        atomicAdd(&g_acc, bsum);
        __threadfence();
        unsigned int prev = atomicInc(&g_count, gridDim.x - 1);
        if (prev == gridDim.x - 1) {
            // last block: all atomicAdds are visible (fence+atomic chain)
            __threadfence();
            double total = atomicAdd(&g_acc, 0.0);  // atomic read
            out[0] = (float)total;
            g_acc = 0.0;                            // reset for next graph replay
            __threadfence();
        }
    }
}

extern "C" void kernel_launch(void* const* d_in, const int* in_sizes, int n_in,
                              void* d_out, int out_size) {
    const float* pos_next = (const float*)d_in[0];
    const float* pos_curr = (const float*)d_in[1];
    const float* pos_prev = (const float*)d_in[2];
    const float* mass     = (const float*)d_in[3];
    const int*   elements = (const int*)d_in[4];
    const float* rest_vol = (const float*)d_in[5];
    const float* rest_inv = (const float*)d_in[6];
    const float* lam      = (const float*)d_in[7];
    const float* mu       = (const float*)d_in[8];
    float* out = (float*)d_out;

    const int V = in_sizes[0] / 3;
    const int E = in_sizes[5];

    // One thread per 2 elements (exact cover of the dominant loop)
    const int H = (E + 1) >> 1;
    int blocks = (H + BLK - 1) / BLK;

    fused_kernel<<<blocks, BLK>>>(pos_next, pos_curr, pos_prev, mass,
                                  elements, rest_vol, rest_inv, lam, mu,
                                  V, E, out);
}

// round 7
// speedup vs baseline: 1.2771x; 1.2771x over previous
#include <cuda_runtime.h>
#include <cuda_bf16.h>
#include <math.h>

#define GRAVITY_C 9.81f
#define W_INERTIA 1.0f
#define W_GRAVITY 0.01f
#define W_STRAIN  1.0f

#define MAX_V 500000
#define EBLK 256          // threads per element block
#define EPB  (2 * EBLK)   // elements per block

__device__ double g_acc = 0.0;
__device__ unsigned int g_count = 0;
__device__ float4 g_pos4[MAX_V];

// -------- block reduction helper (double) --------
__device__ __forceinline__ double block_reduce(double v) {
    #pragma unroll
    for (int off = 16; off > 0; off >>= 1)
        v += __shfl_down_sync(0xFFFFFFFFu, v, off);
    __shared__ double sh[32];
    int lane = threadIdx.x & 31;
    int wid  = threadIdx.x >> 5;
    if (lane == 0) sh[wid] = v;
    __syncthreads();
    int nwarps = (blockDim.x + 31) >> 5;
    v = (threadIdx.x < nwarps) ? sh[threadIdx.x] : 0.0;
    if (wid == 0) {
        #pragma unroll
        for (int off = 16; off > 0; off >>= 1)
            v += __shfl_down_sync(0xFFFFFFFFu, v, off);
    }
    return v;
}

// -------- kernel 1: vertex (inertia + gravity) + pack pos_next into float4 --------
__global__ void vertex_kernel(const float* __restrict__ pos_next,
                              const float* __restrict__ pos_curr,
                              const float* __restrict__ pos_prev,
                              const float* __restrict__ mass,
                              int V) {
    double local = 0.0;
    const double inv3V = 1.0 / (3.0 * (double)V);
    const double invV  = 1.0 / (double)V;
    for (int v = blockIdx.x * blockDim.x + threadIdx.x; v < V;
         v += gridDim.x * blockDim.x) {
        float m  = mass[v];
        float nx = pos_next[3*v+0], ny = pos_next[3*v+1], nz = pos_next[3*v+2];
        float cx = pos_curr[3*v+0], cy = pos_curr[3*v+1], cz = pos_curr[3*v+2];
        float px = pos_prev[3*v+0], py = pos_prev[3*v+1], pz = pos_prev[3*v+2];
        g_pos4[v] = make_float4(nx, ny, nz, 0.0f);
        float ax = nx + px - 2.0f * cx;
        float ay = ny + py - 2.0f * cy;
        float az = nz + pz - 2.0f * cz;
        float a2 = ax*ax + ay*ay + az*az;
        local += (double)(0.5f * m * a2) * (W_INERTIA * inv3V)
               - (double)(m * GRAVITY_C * cy) * (W_GRAVITY * invV);
    }
    double bsum = block_reduce(local);
    if (threadIdx.x == 0) atomicAdd(&g_acc, bsum);
}

// Per-element Neo-Hookean energy from packed positions + smem R
__device__ __forceinline__ float elem_energy4(float4 v0, float4 v1, float4 v2, float4 v3,
                                              const float* __restrict__ R,
                                              float vol, float lam, float mu) {
    float d00 = v1.x - v0.x, d01 = v2.x - v0.x, d02 = v3.x - v0.x;
    float d10 = v1.y - v0.y, d11 = v2.y - v0.y, d12 = v3.y - v0.y;
    float d20 = v1.z - v0.z, d21 = v2.z - v0.z, d22 = v3.z - v0.z;

    float r00 = R[0], r01 = R[1], r02 = R[2];
    float r10 = R[3], r11 = R[4], r12 = R[5];
    float r20 = R[6], r21 = R[7], r22 = R[8];

    float f00 = d00*r00 + d01*r10 + d02*r20;
    float f01 = d00*r01 + d01*r11 + d02*r21;
    float f02 = d00*r02 + d01*r12 + d02*r22;
    float f10 = d10*r00 + d11*r10 + d12*r20;
    float f11 = d10*r01 + d11*r11 + d12*r21;
    float f12 = d10*r02 + d11*r12 + d12*r22;
    float f20 = d20*r00 + d21*r10 + d22*r20;
    float f21 = d20*r01 + d21*r11 + d22*r21;
    float f22 = d20*r02 + d21*r12 + d22*r22;

    float det = f00 * (f11*f22 - f12*f21)
              - f01 * (f10*f22 - f12*f20)
              + f02 * (f10*f21 - f11*f20);
    det = fmaxf(det, 1e-8f);
    float logd = logf(det);

    float tr = f00*f00 + f01*f01 + f02*f02
             + f10*f10 + f11*f11 + f12*f12
             + f20*f20 + f21*f21 + f22*f22;

    float psi = 0.5f * lam * logd * logd - mu * logd + 0.5f * mu * (tr - 3.0f);
    return psi * vol;
}

// -------- kernel 2: element strain (2 elems/thread) + final epilogue --------
__global__ void __launch_bounds__(EBLK)
element_kernel(const int* __restrict__ elements,
               const float* __restrict__ rest_volumes,
               const float* __restrict__ rest_inv,
               const float* __restrict__ lam_p,
               const float* __restrict__ mu_p,
               int E, float* __restrict__ out) {
    __shared__ float sR[EPB * 9];   // 18 KB

    const int blockBase = blockIdx.x * EPB;
    const int nElem = min(EPB, E - blockBase);
    const int nFloats = nElem * 9;

    // coalesced stage of rest_inv into shared (float4 main + scalar tail)
    {
        const float* Rg = rest_inv + (size_t)blockBase * 9;
        const int nVec = nFloats >> 2;  // blockBase*9*4B is 16B-aligned (EPB*9 % 4 == 0)
        const float4* Rg4 = reinterpret_cast<const float4*>(Rg);
        float4* sR4 = reinterpret_cast<float4*>(sR);
        for (int i = threadIdx.x; i < nVec; i += EBLK)
            sR4[i] = Rg4[i];
        for (int i = (nVec << 2) + threadIdx.x; i < nFloats; i += EBLK)
            sR[i] = Rg[i];
    }
    __syncthreads();

    const float lam = lam_p[0];
    const float mu  = mu_p[0];

    const int eA = blockBase + threadIdx.x;          // first half
    const int eB = blockBase + EBLK + threadIdx.x;   // second half
    const int4* __restrict__ elem4 = reinterpret_cast<const int4*>(elements);

    float strain = 0.0f;

    const bool hasA = (eA < E);
    const bool hasB = (eB < E);

    // Issue all long-latency loads up front for maximum MLP
    int4 idxA = hasA ? elem4[eA] : make_int4(0,0,0,0);
    int4 idxB = hasB ? elem4[eB] : make_int4(0,0,0,0);

    float4 a0, a1, a2, a3, b0, b1, b2, b3;
    if (hasA) { a0 = g_pos4[idxA.x]; a1 = g_pos4[idxA.y]; a2 = g_pos4[idxA.z]; a3 = g_pos4[idxA.w]; }
    if (hasB) { b0 = g_pos4[idxB.x]; b1 = g_pos4[idxB.y]; b2 = g_pos4[idxB.z]; b3 = g_pos4[idxB.w]; }

    float volA = hasA ? rest_volumes[eA] : 0.0f;
    float volB = hasB ? rest_volumes[eB] : 0.0f;

    if (hasA) strain += elem_energy4(a0, a1, a2, a3, sR + threadIdx.x * 9, volA, lam, mu);
    if (hasB) strain += elem_energy4(b0, b1, b2, b3, sR + (EBLK + threadIdx.x) * 9, volB, lam, mu);

    double local = (double)strain * (W_STRAIN / (double)E);
    double bsum = block_reduce(local);

    if (threadIdx.x == 0) {
        atomicAdd(&g_acc, bsum);
        __threadfence();
        unsigned int prev = atomicInc(&g_count, gridDim.x - 1);
        if (prev == gridDim.x - 1) {
            __threadfence();
            double total = atomicAdd(&g_acc, 0.0);
            out[0] = (float)total;
            g_acc = 0.0;   // reset for next graph replay (stream-ordered before next launch)
            __threadfence();
        }
    }
}

// Fallback (V > MAX_V): direct gather + own epilogue
__global__ void element_kernel_fallback(const float* __restrict__ pos_next,
                                        const int* __restrict__ elements,
                                        const float* __restrict__ rest_volumes,
                                        const float* __restrict__ rest_inv,
                                        const float* __restrict__ lam_p,
                                        const float* __restrict__ mu_p,
                                        int E, float* __restrict__ out) {
    const float lam = lam_p[0];
    const float mu  = mu_p[0];
    double local = 0.0;
    for (int e = blockIdx.x * blockDim.x + threadIdx.x; e < E;
         e += gridDim.x * blockDim.x) {
        const int4 idx = reinterpret_cast<const int4*>(elements)[e];
        float4 v0 = make_float4(pos_next[3*idx.x], pos_next[3*idx.x+1], pos_next[3*idx.x+2], 0.f);
        float4 v1 = make_float4(pos_next[3*idx.y], pos_next[3*idx.y+1], pos_next[3*idx.y+2], 0.f);
        float4 v2 = make_float4(pos_next[3*idx.z], pos_next[3*idx.z+1], pos_next[3*idx.z+2], 0.f);
        float4 v3 = make_float4(pos_next[3*idx.w], pos_next[3*idx.w+1], pos_next[3*idx.w+2], 0.f);
        float c = elem_energy4(v0, v1, v2, v3, rest_inv + (size_t)e * 9,
                               rest_volumes[e], lam, mu);
        local += (double)c * (W_STRAIN / (double)E);
    }
    double bsum = block_reduce(local);
    if (threadIdx.x == 0) {
        atomicAdd(&g_acc, bsum);
        __threadfence();
        unsigned int prev = atomicInc(&g_count, gridDim.x - 1);
        if (prev == gridDim.x - 1) {
            __threadfence();
            double total = atomicAdd(&g_acc, 0.0);
            out[0] = (float)total;
            g_acc = 0.0;
            __threadfence();
        }
    }
}

extern "C" void kernel_launch(void* const* d_in, const int* in_sizes, int n_in,
                              void* d_out, int out_size) {
    const float* pos_next = (const float*)d_in[0];
    const float* pos_curr = (const float*)d_in[1];
    const float* pos_prev = (const float*)d_in[2];
    const float* mass     = (const float*)d_in[3];
    const int*   elements = (const int*)d_in[4];
    const float* rest_vol = (const float*)d_in[5];
    const float* rest_inv = (const float*)d_in[6];
    const float* lam      = (const float*)d_in[7];
    const float* mu       = (const float*)d_in[8];
    float* out = (float*)d_out;

    const int V = in_sizes[0] / 3;
    const int E = in_sizes[5];

    {
        int threads = 256;
        int blocks  = (V + threads - 1) / threads;
        vertex_kernel<<<blocks, threads>>>(pos_next, pos_curr, pos_prev, mass, V);
    }

    if (V <= MAX_V) {
        int blocks = (E + EPB - 1) / EPB;
        element_kernel<<<blocks, EBLK>>>(elements, rest_vol, rest_inv, lam, mu, E, out);
    } else {
        int threads = 256;
        int blocks  = (E + threads - 1) / threads;
        if (blocks > 8192) blocks = 8192;
        element_kernel_fallback<<<blocks, threads>>>(pos_next, elements, rest_vol,
                                                     rest_inv, lam, mu, E, out);
    }
}

// round 8
// speedup vs baseline: 1.4151x; 1.1081x over previous
#include <cuda_runtime.h>
#include <cuda_bf16.h>
#include <math.h>

#define GRAVITY_C 9.81f
#define W_INERTIA 1.0f
#define W_GRAVITY 0.01f
#define W_STRAIN  1.0f

#define MAX_V 500000
#define EBLK 256          // threads per block
#define EPB  (2 * EBLK)   // elements per block

__device__ double g_acc = 0.0;
__device__ unsigned int g_count = 0;
__device__ float4 g_pos4[MAX_V];

// -------- block reduction helper (double) --------
__device__ __forceinline__ double block_reduce(double v) {
    #pragma unroll
    for (int off = 16; off > 0; off >>= 1)
        v += __shfl_down_sync(0xFFFFFFFFu, v, off);
    __shared__ double sh[32];
    int lane = threadIdx.x & 31;
    int wid  = threadIdx.x >> 5;
    if (lane == 0) sh[wid] = v;
    __syncthreads();
    int nwarps = (blockDim.x + 31) >> 5;
    v = (threadIdx.x < nwarps) ? sh[threadIdx.x] : 0.0;
    if (wid == 0) {
        #pragma unroll
        for (int off = 16; off > 0; off >>= 1)
            v += __shfl_down_sync(0xFFFFFFFFu, v, off);
    }
    return v;
}

// -------- kernel 1: pack pos_next into float4 (vectorized, 4 verts/thread) --------
__global__ void pack_kernel(const float* __restrict__ pos_next, int V) {
    const int c = blockIdx.x * blockDim.x + threadIdx.x;  // chunk of 4 vertices
    const int nChunk = V >> 2;
    if (c < nChunk) {
        const float4* p4 = reinterpret_cast<const float4*>(pos_next);
        float4 q0 = p4[3*c+0];  // v0.x v0.y v0.z v1.x
        float4 q1 = p4[3*c+1];  // v1.y v1.z v2.x v2.y
        float4 q2 = p4[3*c+2];  // v2.z v3.x v3.y v3.z
        int v = 4*c;
        g_pos4[v+0] = make_float4(q0.x, q0.y, q0.z, 0.f);
        g_pos4[v+1] = make_float4(q0.w, q1.x, q1.y, 0.f);
        g_pos4[v+2] = make_float4(q1.z, q1.w, q2.x, 0.f);
        g_pos4[v+3] = make_float4(q2.y, q2.z, q2.w, 0.f);
    } else {
        // tail vertices (V % 4)
        int v = (V & ~3) + (c - nChunk);
        if (c - nChunk < (V & 3))
            g_pos4[v] = make_float4(pos_next[3*v], pos_next[3*v+1], pos_next[3*v+2], 0.f);
    }
}

// Per-element Neo-Hookean energy from packed positions + smem R
__device__ __forceinline__ float elem_energy4(float4 v0, float4 v1, float4 v2, float4 v3,
                                              const float* __restrict__ R,
                                              float vol, float lam, float mu) {
    float d00 = v1.x - v0.x, d01 = v2.x - v0.x, d02 = v3.x - v0.x;
    float d10 = v1.y - v0.y, d11 = v2.y - v0.y, d12 = v3.y - v0.y;
    float d20 = v1.z - v0.z, d21 = v2.z - v0.z, d22 = v3.z - v0.z;

    float r00 = R[0], r01 = R[1], r02 = R[2];
    float r10 = R[3], r11 = R[4], r12 = R[5];
    float r20 = R[6], r21 = R[7], r22 = R[8];

    float f00 = d00*r00 + d01*r10 + d02*r20;
    float f01 = d00*r01 + d01*r11 + d02*r21;
    float f02 = d00*r02 + d01*r12 + d02*r22;
    float f10 = d10*r00 + d11*r10 + d12*r20;
    float f11 = d10*r01 + d11*r11 + d12*r21;
    float f12 = d10*r02 + d11*r12 + d12*r22;
    float f20 = d20*r00 + d21*r10 + d22*r20;
    float f21 = d20*r01 + d21*r11 + d22*r21;
    float f22 = d20*r02 + d21*r12 + d22*r22;

    float det = f00 * (f11*f22 - f12*f21)
              - f01 * (f10*f22 - f12*f20)
              + f02 * (f10*f21 - f11*f20);
    det = fmaxf(det, 1e-8f);
    float logd = logf(det);

    float tr = f00*f00 + f01*f01 + f02*f02
             + f10*f10 + f11*f11 + f12*f12
             + f20*f20 + f21*f21 + f22*f22;

    float psi = 0.5f * lam * logd * logd - mu * logd + 0.5f * mu * (tr - 3.0f);
    return psi * vol;
}

// -------- kernel 2: element strain + vertex inertia/gravity + epilogue --------
__global__ void __launch_bounds__(EBLK)
main_kernel(const float* __restrict__ pos_next,
            const float* __restrict__ pos_curr,
            const float* __restrict__ pos_prev,
            const float* __restrict__ mass,
            const int* __restrict__ elements,
            const float* __restrict__ rest_volumes,
            const float* __restrict__ rest_inv,
            const float* __restrict__ lam_p,
            const float* __restrict__ mu_p,
            int V, int E, float* __restrict__ out) {
    __shared__ float sR[EPB * 9];   // 18 KB

    const int tid = blockIdx.x * EBLK + threadIdx.x;

    // ---- vertex part: one chunk of 4 vertices per thread (vectorized) ----
    float vertf = 0.0f;   // accumulates W-weighted, un-normalized vertex terms
    {
        const int nChunk = V >> 2;
        if (tid < nChunk) {
            const int c = tid;
            const float4* n4 = reinterpret_cast<const float4*>(pos_next);
            const float4* c4 = reinterpret_cast<const float4*>(pos_curr);
            const float4* p4 = reinterpret_cast<const float4*>(pos_prev);
            float4 n0 = n4[3*c+0], n1 = n4[3*c+1], n2 = n4[3*c+2];
            float4 c0 = c4[3*c+0], c1 = c4[3*c+1], c2 = c4[3*c+2];
            float4 p0 = p4[3*c+0], p1 = p4[3*c+1], p2 = p4[3*c+2];
            float4 m4 = reinterpret_cast<const float4*>(mass)[c];

            // accel components for the 12 floats
            float a0x = n0.x + p0.x - 2.f*c0.x, a0y = n0.y + p0.y - 2.f*c0.y, a0z = n0.z + p0.z - 2.f*c0.z;
            float a1x = n0.w + p0.w - 2.f*c0.w, a1y = n1.x + p1.x - 2.f*c1.x, a1z = n1.y + p1.y - 2.f*c1.y;
            float a2x = n1.z + p1.z - 2.f*c1.z, a2y = n1.w + p1.w - 2.f*c1.w, a2z = n2.x + p2.x - 2.f*c2.x;
            float a3x = n2.y + p2.y - 2.f*c2.y, a3y = n2.z + p2.z - 2.f*c2.z, a3z = n2.w + p2.w - 2.f*c2.w;

            float s0 = a0x*a0x + a0y*a0y + a0z*a0z;
            float s1 = a1x*a1x + a1y*a1y + a1z*a1z;
            float s2 = a2x*a2x + a2y*a2y + a2z*a2z;
            float s3 = a3x*a3x + a3y*a3y + a3z*a3z;

            // y-coords of pos_curr for the 4 vertices: c0.y, c1.x, c1.w, c2.z
            float inert = 0.5f * (m4.x*s0 + m4.y*s1 + m4.z*s2 + m4.w*s3);
            float grav  = m4.x*c0.y + m4.y*c1.x + m4.z*c1.w + m4.w*c2.z;
            vertf = inert * (W_INERTIA / 3.0f) - grav * (W_GRAVITY * GRAVITY_C);
        } else {
            // scalar tail (V % 4 vertices)
            int t = tid - (V >> 2);
            if (t < (V & 3)) {
                int v = (V & ~3) + t;
                float m  = mass[v];
                float ax = pos_next[3*v+0] + pos_prev[3*v+0] - 2.f*pos_curr[3*v+0];
                float ay = pos_next[3*v+1] + pos_prev[3*v+1] - 2.f*pos_curr[3*v+1];
                float az = pos_next[3*v+2] + pos_prev[3*v+2] - 2.f*pos_curr[3*v+2];
                float cy = pos_curr[3*v+1];
                vertf = 0.5f*m*(ax*ax+ay*ay+az*az) * (W_INERTIA / 3.0f)
                      - m*cy * (W_GRAVITY * GRAVITY_C);
            }
        }
    }

    // ---- element part: 2 elements per thread ----
    const int blockBase = blockIdx.x * EPB;
    {
        const int nElem = min(EPB, E - blockBase);
        const int nFloats = nElem * 9;
        const float* Rg = rest_inv + (size_t)blockBase * 9;
        const int nVec = nFloats >> 2;
        const float4* Rg4 = reinterpret_cast<const float4*>(Rg);
        float4* sR4 = reinterpret_cast<float4*>(sR);
        for (int i = threadIdx.x; i < nVec; i += EBLK)
            sR4[i] = Rg4[i];
        for (int i = (nVec << 2) + threadIdx.x; i < nFloats; i += EBLK)
            sR[i] = Rg[i];
    }
    __syncthreads();

    const float lam = lam_p[0];
    const float mu  = mu_p[0];

    const int eA = blockBase + threadIdx.x;
    const int eB = blockBase + EBLK + threadIdx.x;
    const int4* __restrict__ elem4 = reinterpret_cast<const int4*>(elements);

    float strain = 0.0f;
    const bool hasA = (eA < E);
    const bool hasB = (eB < E);

    int4 idxA = hasA ? elem4[eA] : make_int4(0,0,0,0);
    int4 idxB = hasB ? elem4[eB] : make_int4(0,0,0,0);

    float4 a0, a1, a2, a3, b0, b1, b2, b3;
    if (hasA) { a0 = g_pos4[idxA.x]; a1 = g_pos4[idxA.y]; a2 = g_pos4[idxA.z]; a3 = g_pos4[idxA.w]; }
    if (hasB) { b0 = g_pos4[idxB.x]; b1 = g_pos4[idxB.y]; b2 = g_pos4[idxB.z]; b3 = g_pos4[idxB.w]; }

    float volA = hasA ? rest_volumes[eA] : 0.0f;
    float volB = hasB ? rest_volumes[eB] : 0.0f;

    if (hasA) strain += elem_energy4(a0, a1, a2, a3, sR + threadIdx.x * 9, volA, lam, mu);
    if (hasB) strain += elem_energy4(b0, b1, b2, b3, sR + (EBLK + threadIdx.x) * 9, volB, lam, mu);

    // ---- combine, reduce, epilogue ----
    double local = (double)strain * (W_STRAIN / (double)E)
                 + (double)vertf * (1.0 / (double)V);
    double bsum = block_reduce(local);

    if (threadIdx.x == 0) {
        atomicAdd(&g_acc, bsum);
        __threadfence();
        unsigned int prev = atomicInc(&g_count, gridDim.x - 1);
        if (prev == gridDim.x - 1) {
            __threadfence();
            double total = atomicAdd(&g_acc, 0.0);
            out[0] = (float)total;
            g_acc = 0.0;   // reset for next graph replay
            __threadfence();
        }
    }
}

extern "C" void kernel_launch(void* const* d_in, const int* in_sizes, int n_in,
                              void* d_out, int out_size) {
    const float* pos_next = (const float*)d_in[0];
    const float* pos_curr = (const float*)d_in[1];
    const float* pos_prev = (const float*)d_in[2];
    const float* mass     = (const float*)d_in[3];
    const int*   elements = (const int*)d_in[4];
    const float* rest_vol = (const float*)d_in[5];
    const float* rest_inv = (const float*)d_in[6];
    const float* lam      = (const float*)d_in[7];
    const float* mu       = (const float*)d_in[8];
    float* out = (float*)d_out;

    const int V = in_sizes[0] / 3;
    const int E = in_sizes[5];

    {
        // threads must cover V/4 chunks + tail
        int work = (V >> 2) + 4;
        int blocks = (work + 255) / 256;
        pack_kernel<<<blocks, 256>>>(pos_next, V);
    }
    {
        int blocksE = (E + EPB - 1) / EPB;
        // must also cover vertex chunks: (V/4 + 4) threads
        int blocksV = ((V >> 2) + 4 + EBLK - 1) / EBLK;
        int blocks = blocksE > blocksV ? blocksE : blocksV;
        main_kernel<<<blocks, EBLK>>>(pos_next, pos_curr, pos_prev, mass,
                                      elements, rest_vol, rest_inv, lam, mu,
                                      V, E, out);
    }
}

// round 9
// speedup vs baseline: 1.5237x; 1.0767x over previous
#include <cuda_runtime.h>
#include <cuda_bf16.h>
#include <math.h>

#define GRAVITY_C 9.81f
#define W_INERTIA 1.0f
#define W_GRAVITY 0.01f
#define W_STRAIN  1.0f

#define MAX_V 500000
#define EBLK 256          // threads per block
#define EPB  (2 * EBLK)   // elements per block

__device__ double g_acc = 0.0;
__device__ unsigned int g_count = 0;
__device__ float4 g_pos4[MAX_V];

// -------- block reduction helper (double) --------
__device__ __forceinline__ double block_reduce(double v) {
    #pragma unroll
    for (int off = 16; off > 0; off >>= 1)
        v += __shfl_down_sync(0xFFFFFFFFu, v, off);
    __shared__ double sh[32];
    int lane = threadIdx.x & 31;
    int wid  = threadIdx.x >> 5;
    if (lane == 0) sh[wid] = v;
    __syncthreads();
    int nwarps = (blockDim.x + 31) >> 5;
    v = (threadIdx.x < nwarps) ? sh[threadIdx.x] : 0.0;
    if (wid == 0) {
        #pragma unroll
        for (int off = 16; off > 0; off >>= 1)
            v += __shfl_down_sync(0xFFFFFFFFu, v, off);
    }
    return v;
}

// -------- kernel 1: vertex inertia/gravity (vectorized) + pack pos_next into float4 --------
__global__ void vertex_pack_kernel(const float* __restrict__ pos_next,
                                   const float* __restrict__ pos_curr,
                                   const float* __restrict__ pos_prev,
                                   const float* __restrict__ mass,
                                   int V) {
    const int c = blockIdx.x * blockDim.x + threadIdx.x;  // chunk of 4 vertices
    const int nChunk = V >> 2;
    float vertf = 0.0f;

    if (c < nChunk) {
        const float4* n4 = reinterpret_cast<const float4*>(pos_next);
        const float4* c4 = reinterpret_cast<const float4*>(pos_curr);
        const float4* p4 = reinterpret_cast<const float4*>(pos_prev);
        float4 n0 = n4[3*c+0], n1 = n4[3*c+1], n2 = n4[3*c+2];
        float4 c0 = c4[3*c+0], c1 = c4[3*c+1], c2 = c4[3*c+2];
        float4 p0 = p4[3*c+0], p1 = p4[3*c+1], p2 = p4[3*c+2];
        float4 m4 = reinterpret_cast<const float4*>(mass)[c];

        // pack positions for the element-kernel gather
        int v = 4*c;
        g_pos4[v+0] = make_float4(n0.x, n0.y, n0.z, 0.f);
        g_pos4[v+1] = make_float4(n0.w, n1.x, n1.y, 0.f);
        g_pos4[v+2] = make_float4(n1.z, n1.w, n2.x, 0.f);
        g_pos4[v+3] = make_float4(n2.y, n2.z, n2.w, 0.f);

        float a0x = n0.x + p0.x - 2.f*c0.x, a0y = n0.y + p0.y - 2.f*c0.y, a0z = n0.z + p0.z - 2.f*c0.z;
        float a1x = n0.w + p0.w - 2.f*c0.w, a1y = n1.x + p1.x - 2.f*c1.x, a1z = n1.y + p1.y - 2.f*c1.y;
        float a2x = n1.z + p1.z - 2.f*c1.z, a2y = n1.w + p1.w - 2.f*c1.w, a2z = n2.x + p2.x - 2.f*c2.x;
        float a3x = n2.y + p2.y - 2.f*c2.y, a3y = n2.z + p2.z - 2.f*c2.z, a3z = n2.w + p2.w - 2.f*c2.w;

        float s0 = a0x*a0x + a0y*a0y + a0z*a0z;
        float s1 = a1x*a1x + a1y*a1y + a1z*a1z;
        float s2 = a2x*a2x + a2y*a2y + a2z*a2z;
        float s3 = a3x*a3x + a3y*a3y + a3z*a3z;

        float inert = 0.5f * (m4.x*s0 + m4.y*s1 + m4.z*s2 + m4.w*s3);
        float grav  = m4.x*c0.y + m4.y*c1.x + m4.z*c1.w + m4.w*c2.z;
        vertf = inert * (W_INERTIA / 3.0f) - grav * (W_GRAVITY * GRAVITY_C);
    } else {
        int t = c - nChunk;
        if (t < (V & 3)) {
            int v = (V & ~3) + t;
            g_pos4[v] = make_float4(pos_next[3*v], pos_next[3*v+1], pos_next[3*v+2], 0.f);
            float m  = mass[v];
            float ax = pos_next[3*v+0] + pos_prev[3*v+0] - 2.f*pos_curr[3*v+0];
            float ay = pos_next[3*v+1] + pos_prev[3*v+1] - 2.f*pos_curr[3*v+1];
            float az = pos_next[3*v+2] + pos_prev[3*v+2] - 2.f*pos_curr[3*v+2];
            float cy = pos_curr[3*v+1];
            vertf = 0.5f*m*(ax*ax+ay*ay+az*az) * (W_INERTIA / 3.0f)
                  - m*cy * (W_GRAVITY * GRAVITY_C);
        }
    }

    double local = (double)vertf * (1.0 / (double)V);
    double bsum = block_reduce(local);
    if (threadIdx.x == 0) atomicAdd(&g_acc, bsum);
}

// Per-element Neo-Hookean energy from packed positions + smem R
__device__ __forceinline__ float elem_energy4(float4 v0, float4 v1, float4 v2, float4 v3,
                                              const float* __restrict__ R,
                                              float vol, float lam, float mu) {
    float d00 = v1.x - v0.x, d01 = v2.x - v0.x, d02 = v3.x - v0.x;
    float d10 = v1.y - v0.y, d11 = v2.y - v0.y, d12 = v3.y - v0.y;
    float d20 = v1.z - v0.z, d21 = v2.z - v0.z, d22 = v3.z - v0.z;

    float r00 = R[0], r01 = R[1], r02 = R[2];
    float r10 = R[3], r11 = R[4], r12 = R[5];
    float r20 = R[6], r21 = R[7], r22 = R[8];

    float f00 = d00*r00 + d01*r10 + d02*r20;
    float f01 = d00*r01 + d01*r11 + d02*r21;
    float f02 = d00*r02 + d01*r12 + d02*r22;
    float f10 = d10*r00 + d11*r10 + d12*r20;
    float f11 = d10*r01 + d11*r11 + d12*r21;
    float f12 = d10*r02 + d11*r12 + d12*r22;
    float f20 = d20*r00 + d21*r10 + d22*r20;
    float f21 = d20*r01 + d21*r11 + d22*r21;
    float f22 = d20*r02 + d21*r12 + d22*r22;

    float det = f00 * (f11*f22 - f12*f21)
              - f01 * (f10*f22 - f12*f20)
              + f02 * (f10*f21 - f11*f20);
    det = fmaxf(det, 1e-8f);
    float logd = logf(det);

    float tr = f00*f00 + f01*f01 + f02*f02
             + f10*f10 + f11*f11 + f12*f12
             + f20*f20 + f21*f21 + f22*f22;

    float psi = 0.5f * lam * logd * logd - mu * logd + 0.5f * mu * (tr - 3.0f);
    return psi * vol;
}

// -------- kernel 2: element strain (2 elems/thread) + final epilogue --------
__global__ void __launch_bounds__(EBLK)
element_kernel(const int* __restrict__ elements,
               const float* __restrict__ rest_volumes,
               const float* __restrict__ rest_inv,
               const float* __restrict__ lam_p,
               const float* __restrict__ mu_p,
               int E, float* __restrict__ out) {
    __shared__ float sR[EPB * 9];   // 18 KB

    const int blockBase = blockIdx.x * EPB;
    const int eA = blockBase + threadIdx.x;
    const int eB = blockBase + EBLK + threadIdx.x;
    const bool hasA = (eA < E);
    const bool hasB = (eB < E);

    // ---- prefetch long-latency streamed loads BEFORE staging (hide idx DRAM latency) ----
    const int4* __restrict__ elem4 = reinterpret_cast<const int4*>(elements);
    int4 idxA = hasA ? elem4[eA] : make_int4(0,0,0,0);
    int4 idxB = hasB ? elem4[eB] : make_int4(0,0,0,0);
    float volA = hasA ? rest_volumes[eA] : 0.0f;
    float volB = hasB ? rest_volumes[eB] : 0.0f;

    // ---- coalesced stage of rest_inv into shared ----
    {
        const int nElem = min(EPB, E - blockBase);
        const int nFloats = nElem * 9;
        const float* Rg = rest_inv + (size_t)blockBase * 9;
        const int nVec = nFloats >> 2;
        const float4* Rg4 = reinterpret_cast<const float4*>(Rg);
        float4* sR4 = reinterpret_cast<float4*>(sR);
        for (int i = threadIdx.x; i < nVec; i += EBLK)
            sR4[i] = Rg4[i];
        for (int i = (nVec << 2) + threadIdx.x; i < nFloats; i += EBLK)
            sR[i] = Rg[i];
    }
    __syncthreads();

    // ---- gathers (the wavefront-bound part) ----
    float4 a0, a1, a2, a3, b0, b1, b2, b3;
    if (hasA) { a0 = g_pos4[idxA.x]; a1 = g_pos4[idxA.y]; a2 = g_pos4[idxA.z]; a3 = g_pos4[idxA.w]; }
    if (hasB) { b0 = g_pos4[idxB.x]; b1 = g_pos4[idxB.y]; b2 = g_pos4[idxB.z]; b3 = g_pos4[idxB.w]; }

    const float lam = lam_p[0];
    const float mu  = mu_p[0];

    float strain = 0.0f;
    if (hasA) strain += elem_energy4(a0, a1, a2, a3, sR + threadIdx.x * 9, volA, lam, mu);
    if (hasB) strain += elem_energy4(b0, b1, b2, b3, sR + (EBLK + threadIdx.x) * 9, volB, lam, mu);

    double local = (double)strain * (W_STRAIN / (double)E);
    double bsum = block_reduce(local);

    if (threadIdx.x == 0) {
        atomicAdd(&g_acc, bsum);
        __threadfence();
        unsigned int prev = atomicInc(&g_count, gridDim.x - 1);
        if (prev == gridDim.x - 1) {
            __threadfence();
            double total = atomicAdd(&g_acc, 0.0);
            out[0] = (float)total;
            g_acc = 0.0;   // reset for next graph replay
            __threadfence();
        }
    }
}

extern "C" void kernel_launch(void* const* d_in, const int* in_sizes, int n_in,
                              void* d_out, int out_size) {
    const float* pos_next = (const float*)d_in[0];
    const float* pos_curr = (const float*)d_in[1];
    const float* pos_prev = (const float*)d_in[2];
    const float* mass     = (const float*)d_in[3];
    const int*   elements = (const int*)d_in[4];
    const float* rest_vol = (const float*)d_in[5];
    const float* rest_inv = (const float*)d_in[6];
    const float* lam      = (const float*)d_in[7];
    const float* mu       = (const float*)d_in[8];
    float* out = (float*)d_out;

    const int V = in_sizes[0] / 3;
    const int E = in_sizes[5];

    {
        int work = (V >> 2) + 4;  // chunks + tail
        int blocks = (work + 255) / 256;
        vertex_pack_kernel<<<blocks, 256>>>(pos_next, pos_curr, pos_prev, mass, V);
    }
    {
        int blocks = (E + EPB - 1) / EPB;
        element_kernel<<<blocks, EBLK>>>(elements, rest_vol, rest_inv, lam, mu, E, out);
    }
}

// round 10
// speedup vs baseline: 1.5538x; 1.0198x over previous
#include <cuda_runtime.h>
#include <cuda_bf16.h>
#include <math.h>

#define GRAVITY_C 9.81f
#define W_INERTIA 1.0f
#define W_GRAVITY 0.01f
#define W_STRAIN  1.0f

#define MAX_V 500000
#define EBLK 256          // threads per block
#define EPB  (2 * EBLK)   // elements per block

__device__ double g_acc = 0.0;
__device__ unsigned int g_count = 0;
__device__ float4 g_pos4[MAX_V];

// -------- block reduction helper (double) --------
__device__ __forceinline__ double block_reduce(double v) {
    #pragma unroll
    for (int off = 16; off > 0; off >>= 1)
        v += __shfl_down_sync(0xFFFFFFFFu, v, off);
    __shared__ double sh[32];
    int lane = threadIdx.x & 31;
    int wid  = threadIdx.x >> 5;
    if (lane == 0) sh[wid] = v;
    __syncthreads();
    int nwarps = (blockDim.x + 31) >> 5;
    v = (threadIdx.x < nwarps) ? sh[threadIdx.x] : 0.0;
    if (wid == 0) {
        #pragma unroll
        for (int off = 16; off > 0; off >>= 1)
            v += __shfl_down_sync(0xFFFFFFFFu, v, off);
    }
    return v;
}

// -------- kernel 1 (primary): vertex terms + pack pos_next into float4 --------
__global__ void vertex_pack_kernel(const float* __restrict__ pos_next,
                                   const float* __restrict__ pos_curr,
                                   const float* __restrict__ pos_prev,
                                   const float* __restrict__ mass,
                                   int V) {
    const int c = blockIdx.x * blockDim.x + threadIdx.x;  // chunk of 4 vertices
    const int nChunk = V >> 2;
    float vertf = 0.0f;

    if (c < nChunk) {
        const float4* n4 = reinterpret_cast<const float4*>(pos_next);
        const float4* c4 = reinterpret_cast<const float4*>(pos_curr);
        const float4* p4 = reinterpret_cast<const float4*>(pos_prev);
        float4 n0 = n4[3*c+0], n1 = n4[3*c+1], n2 = n4[3*c+2];
        float4 c0 = c4[3*c+0], c1 = c4[3*c+1], c2 = c4[3*c+2];
        float4 p0 = p4[3*c+0], p1 = p4[3*c+1], p2 = p4[3*c+2];
        float4 m4 = reinterpret_cast<const float4*>(mass)[c];

        int v = 4*c;
        g_pos4[v+0] = make_float4(n0.x, n0.y, n0.z, 0.f);
        g_pos4[v+1] = make_float4(n0.w, n1.x, n1.y, 0.f);
        g_pos4[v+2] = make_float4(n1.z, n1.w, n2.x, 0.f);
        g_pos4[v+3] = make_float4(n2.y, n2.z, n2.w, 0.f);

        float a0x = n0.x + p0.x - 2.f*c0.x, a0y = n0.y + p0.y - 2.f*c0.y, a0z = n0.z + p0.z - 2.f*c0.z;
        float a1x = n0.w + p0.w - 2.f*c0.w, a1y = n1.x + p1.x - 2.f*c1.x, a1z = n1.y + p1.y - 2.f*c1.y;
        float a2x = n1.z + p1.z - 2.f*c1.z, a2y = n1.w + p1.w - 2.f*c1.w, a2z = n2.x + p2.x - 2.f*c2.x;
        float a3x = n2.y + p2.y - 2.f*c2.y, a3y = n2.z + p2.z - 2.f*c2.z, a3z = n2.w + p2.w - 2.f*c2.w;

        float s0 = a0x*a0x + a0y*a0y + a0z*a0z;
        float s1 = a1x*a1x + a1y*a1y + a1z*a1z;
        float s2 = a2x*a2x + a2y*a2y + a2z*a2z;
        float s3 = a3x*a3x + a3y*a3y + a3z*a3z;

        float inert = 0.5f * (m4.x*s0 + m4.y*s1 + m4.z*s2 + m4.w*s3);
        float grav  = m4.x*c0.y + m4.y*c1.x + m4.z*c1.w + m4.w*c2.z;
        vertf = inert * (W_INERTIA / 3.0f) - grav * (W_GRAVITY * GRAVITY_C);
    } else {
        int t = c - nChunk;
        if (t < (V & 3)) {
            int v = (V & ~3) + t;
            g_pos4[v] = make_float4(pos_next[3*v], pos_next[3*v+1], pos_next[3*v+2], 0.f);
            float m  = mass[v];
            float ax = pos_next[3*v+0] + pos_prev[3*v+0] - 2.f*pos_curr[3*v+0];
            float ay = pos_next[3*v+1] + pos_prev[3*v+1] - 2.f*pos_curr[3*v+1];
            float az = pos_next[3*v+2] + pos_prev[3*v+2] - 2.f*pos_curr[3*v+2];
            float cy = pos_curr[3*v+1];
            vertf = 0.5f*m*(ax*ax+ay*ay+az*az) * (W_INERTIA / 3.0f)
                  - m*cy * (W_GRAVITY * GRAVITY_C);
        }
    }

    double local = (double)vertf * (1.0 / (double)V);
    double bsum = block_reduce(local);
    if (threadIdx.x == 0) atomicAdd(&g_acc, bsum);

    // signal dependent grid: our g_pos4 stores + g_acc add are done
    asm volatile("griddepcontrol.launch_dependents;");
}

// Per-element Neo-Hookean energy from packed positions + smem R
__device__ __forceinline__ float elem_energy4(float4 v0, float4 v1, float4 v2, float4 v3,
                                              const float* __restrict__ R,
                                              float vol, float lam, float mu) {
    float d00 = v1.x - v0.x, d01 = v2.x - v0.x, d02 = v3.x - v0.x;
    float d10 = v1.y - v0.y, d11 = v2.y - v0.y, d12 = v3.y - v0.y;
    float d20 = v1.z - v0.z, d21 = v2.z - v0.z, d22 = v3.z - v0.z;

    float r00 = R[0], r01 = R[1], r02 = R[2];
    float r10 = R[3], r11 = R[4], r12 = R[5];
    float r20 = R[6], r21 = R[7], r22 = R[8];

    float f00 = d00*r00 + d01*r10 + d02*r20;
    float f01 = d00*r01 + d01*r11 + d02*r21;
    float f02 = d00*r02 + d01*r12 + d02*r22;
    float f10 = d10*r00 + d11*r10 + d12*r20;
    float f11 = d10*r01 + d11*r11 + d12*r21;
    float f12 = d10*r02 + d11*r12 + d12*r22;
    float f20 = d20*r00 + d21*r10 + d22*r20;
    float f21 = d20*r01 + d21*r11 + d22*r21;
    float f22 = d20*r02 + d21*r12 + d22*r22;

    float det = f00 * (f11*f22 - f12*f21)
              - f01 * (f10*f22 - f12*f20)
              + f02 * (f10*f21 - f11*f20);
    det = fmaxf(det, 1e-8f);
    float logd = logf(det);

    float tr = f00*f00 + f01*f01 + f02*f02
             + f10*f10 + f11*f11 + f12*f12
             + f20*f20 + f21*f21 + f22*f22;

    float psi = 0.5f * lam * logd * logd - mu * logd + 0.5f * mu * (tr - 3.0f);
    return psi * vol;
}

// -------- kernel 2 (secondary, PDL): element strain + final epilogue --------
__global__ void __launch_bounds__(EBLK, 4)
element_kernel(const int* __restrict__ elements,
               const float* __restrict__ rest_volumes,
               const float* __restrict__ rest_inv,
               const float* __restrict__ lam_p,
               const float* __restrict__ mu_p,
               int E, float* __restrict__ out) {
    __shared__ float sR[EPB * 9];   // 18 KB

    const int blockBase = blockIdx.x * EPB;
    const int eA = blockBase + threadIdx.x;
    const int eB = blockBase + EBLK + threadIdx.x;
    const bool hasA = (eA < E);
    const bool hasB = (eB < E);

    // ---- phase 1 (overlaps with primary kernel): streamed prefetch + staging ----
    const int4* __restrict__ elem4 = reinterpret_cast<const int4*>(elements);
    int4 idxA = hasA ? elem4[eA] : make_int4(0,0,0,0);
    int4 idxB = hasB ? elem4[eB] : make_int4(0,0,0,0);
    float volA = hasA ? rest_volumes[eA] : 0.0f;
    float volB = hasB ? rest_volumes[eB] : 0.0f;

    {
        const int nElem = min(EPB, E - blockBase);
        const int nFloats = nElem * 9;
        const float* Rg = rest_inv + (size_t)blockBase * 9;
        const int nVec = nFloats >> 2;
        const float4* Rg4 = reinterpret_cast<const float4*>(Rg);
        float4* sR4 = reinterpret_cast<float4*>(sR);
        for (int i = threadIdx.x; i < nVec; i += EBLK)
            sR4[i] = Rg4[i];
        for (int i = (nVec << 2) + threadIdx.x; i < nFloats; i += EBLK)
            sR[i] = Rg[i];
    }
    __syncthreads();

    // ---- wait for primary grid (g_pos4 ready) ----
    asm volatile("griddepcontrol.wait;" ::: "memory");

    // ---- phase 2: gathers (the wavefront-bound part) ----
    float4 a0, a1, a2, a3, b0, b1, b2, b3;
    if (hasA) { a0 = g_pos4[idxA.x]; a1 = g_pos4[idxA.y]; a2 = g_pos4[idxA.z]; a3 = g_pos4[idxA.w]; }
    if (hasB) { b0 = g_pos4[idxB.x]; b1 = g_pos4[idxB.y]; b2 = g_pos4[idxB.z]; b3 = g_pos4[idxB.w]; }

    const float lam = lam_p[0];
    const float mu  = mu_p[0];

    float strain = 0.0f;
    if (hasA) strain += elem_energy4(a0, a1, a2, a3, sR + threadIdx.x * 9, volA, lam, mu);
    if (hasB) strain += elem_energy4(b0, b1, b2, b3, sR + (EBLK + threadIdx.x) * 9, volB, lam, mu);

    double local = (double)strain * (W_STRAIN / (double)E);
    double bsum = block_reduce(local);

    if (threadIdx.x == 0) {
        atomicAdd(&g_acc, bsum);
        __threadfence();
        unsigned int prev = atomicInc(&g_count, gridDim.x - 1);
        if (prev == gridDim.x - 1) {
            __threadfence();
            double total = atomicAdd(&g_acc, 0.0);
            out[0] = (float)total;
            g_acc = 0.0;   // reset for next graph replay
            __threadfence();
        }
    }
}

extern "C" void kernel_launch(void* const* d_in, const int* in_sizes, int n_in,
                              void* d_out, int out_size) {
    const float* pos_next = (const float*)d_in[0];
    const float* pos_curr = (const float*)d_in[1];
    const float* pos_prev = (const float*)d_in[2];
    const float* mass     = (const float*)d_in[3];
    const int*   elements = (const int*)d_in[4];
    const float* rest_vol = (const float*)d_in[5];
    const float* rest_inv = (const float*)d_in[6];
    const float* lam      = (const float*)d_in[7];
    const float* mu       = (const float*)d_in[8];
    float* out = (float*)d_out;

    const int V = in_sizes[0] / 3;
    const int E = in_sizes[5];

    // primary
    {
        int work = (V >> 2) + 4;
        int blocks = (work + 255) / 256;
        vertex_pack_kernel<<<blocks, 256>>>(pos_next, pos_curr, pos_prev, mass, V);
    }

    // secondary with programmatic dependent launch (overlaps its staging with primary)
    {
        int blocks = (E + EPB - 1) / EPB;
        cudaLaunchConfig_t cfg = {};
        cfg.gridDim  = dim3((unsigned)blocks, 1, 1);
        cfg.blockDim = dim3(EBLK, 1, 1);
        cudaLaunchAttribute attrs[1];
        attrs[0].id = cudaLaunchAttributeProgrammaticStreamSerialization;
        attrs[0].val.programmaticStreamSerializationAllowed = 1;
        cfg.attrs = attrs;
        cfg.numAttrs = 1;
        cudaLaunchKernelEx(&cfg, element_kernel,
                           elements, rest_vol, rest_inv, lam, mu, E, out);
    }
}

// round 11
// speedup vs baseline: 1.6178x; 1.0412x over previous
#include <cuda_runtime.h>
#include <cuda_bf16.h>
#include <math.h>

#define GRAVITY_C 9.81f
#define W_INERTIA 1.0f
#define W_GRAVITY 0.01f
#define W_STRAIN  1.0f

#define MAX_V 500000
#define EBLK 256          // threads per block
#define EPB  (2 * EBLK)   // elements per block

__device__ double g_acc = 0.0;
__device__ unsigned int g_count = 0;
__device__ float4 g_pos4[MAX_V];

// L2-only gather load (no L1 line allocation)
__device__ __forceinline__ float4 ldcg_f4(const float4* p) {
    float4 v;
    asm volatile("ld.global.cg.v4.f32 {%0,%1,%2,%3}, [%4];"
                 : "=f"(v.x), "=f"(v.y), "=f"(v.z), "=f"(v.w) : "l"(p));
    return v;
}

// -------- block reduction helper (double) --------
__device__ __forceinline__ double block_reduce(double v) {
    #pragma unroll
    for (int off = 16; off > 0; off >>= 1)
        v += __shfl_down_sync(0xFFFFFFFFu, v, off);
    __shared__ double sh[32];
    int lane = threadIdx.x & 31;
    int wid  = threadIdx.x >> 5;
    if (lane == 0) sh[wid] = v;
    __syncthreads();
    int nwarps = (blockDim.x + 31) >> 5;
    v = (threadIdx.x < nwarps) ? sh[threadIdx.x] : 0.0;
    if (wid == 0) {
        #pragma unroll
        for (int off = 16; off > 0; off >>= 1)
            v += __shfl_down_sync(0xFFFFFFFFu, v, off);
    }
    return v;
}

// -------- kernel 1 (primary): pure pack of pos_next into float4 --------
__global__ void pack_kernel(const float* __restrict__ pos_next, int V) {
    const int c = blockIdx.x * blockDim.x + threadIdx.x;  // chunk of 4 vertices
    const int nChunk = V >> 2;
    if (c < nChunk) {
        const float4* p4 = reinterpret_cast<const float4*>(pos_next);
        float4 q0 = p4[3*c+0];
        float4 q1 = p4[3*c+1];
        float4 q2 = p4[3*c+2];
        int v = 4*c;
        g_pos4[v+0] = make_float4(q0.x, q0.y, q0.z, 0.f);
        g_pos4[v+1] = make_float4(q0.w, q1.x, q1.y, 0.f);
        g_pos4[v+2] = make_float4(q1.z, q1.w, q2.x, 0.f);
        g_pos4[v+3] = make_float4(q2.y, q2.z, q2.w, 0.f);
    } else {
        int t = c - nChunk;
        if (t < (V & 3)) {
            int v = (V & ~3) + t;
            g_pos4[v] = make_float4(pos_next[3*v], pos_next[3*v+1], pos_next[3*v+2], 0.f);
        }
    }
    asm volatile("griddepcontrol.launch_dependents;");
}

// Per-element Neo-Hookean energy from packed positions + smem R
__device__ __forceinline__ float elem_energy4(float4 v0, float4 v1, float4 v2, float4 v3,
                                              const float* __restrict__ R,
                                              float vol, float lam, float mu) {
    float d00 = v1.x - v0.x, d01 = v2.x - v0.x, d02 = v3.x - v0.x;
    float d10 = v1.y - v0.y, d11 = v2.y - v0.y, d12 = v3.y - v0.y;
    float d20 = v1.z - v0.z, d21 = v2.z - v0.z, d22 = v3.z - v0.z;

    float r00 = R[0], r01 = R[1], r02 = R[2];
    float r10 = R[3], r11 = R[4], r12 = R[5];
    float r20 = R[6], r21 = R[7], r22 = R[8];

    float f00 = d00*r00 + d01*r10 + d02*r20;
    float f01 = d00*r01 + d01*r11 + d02*r21;
    float f02 = d00*r02 + d01*r12 + d02*r22;
    float f10 = d10*r00 + d11*r10 + d12*r20;
    float f11 = d10*r01 + d11*r11 + d12*r21;
    float f12 = d10*r02 + d11*r12 + d12*r22;
    float f20 = d20*r00 + d21*r10 + d22*r20;
    float f21 = d20*r01 + d21*r11 + d22*r21;
    float f22 = d20*r02 + d21*r12 + d22*r22;

    float det = f00 * (f11*f22 - f12*f21)
              - f01 * (f10*f22 - f12*f20)
              + f02 * (f10*f21 - f11*f20);
    det = fmaxf(det, 1e-8f);
    float logd = logf(det);

    float tr = f00*f00 + f01*f01 + f02*f02
             + f10*f10 + f11*f11 + f12*f12
             + f20*f20 + f21*f21 + f22*f22;

    float psi = 0.5f * lam * logd * logd - mu * logd + 0.5f * mu * (tr - 3.0f);
    return psi * vol;
}

// -------- kernel 2 (secondary, PDL): element blocks + vertex tail blocks --------
__global__ void __launch_bounds__(EBLK, 4)
main_kernel(const float* __restrict__ pos_next,
            const float* __restrict__ pos_curr,
            const float* __restrict__ pos_prev,
            const float* __restrict__ mass,
            const int* __restrict__ elements,
            const float* __restrict__ rest_volumes,
            const float* __restrict__ rest_inv,
            const float* __restrict__ lam_p,
            const float* __restrict__ mu_p,
            int V, int E, int nEBlocks, float* __restrict__ out) {
    double local = 0.0;

    if ((int)blockIdx.x >= nEBlocks) {
        // ---------- vertex block: inertia + gravity (no dependency on pack) ----------
        const int c = (blockIdx.x - nEBlocks) * EBLK + threadIdx.x;  // chunk of 4 verts
        const int nChunk = V >> 2;
        float vertf = 0.0f;
        if (c < nChunk) {
            const float4* n4 = reinterpret_cast<const float4*>(pos_next);
            const float4* c4 = reinterpret_cast<const float4*>(pos_curr);
            const float4* p4 = reinterpret_cast<const float4*>(pos_prev);
            float4 n0 = n4[3*c+0], n1 = n4[3*c+1], n2 = n4[3*c+2];
            float4 c0 = c4[3*c+0], c1 = c4[3*c+1], c2 = c4[3*c+2];
            float4 p0 = p4[3*c+0], p1 = p4[3*c+1], p2 = p4[3*c+2];
            float4 m4 = reinterpret_cast<const float4*>(mass)[c];

            float a0x = n0.x + p0.x - 2.f*c0.x, a0y = n0.y + p0.y - 2.f*c0.y, a0z = n0.z + p0.z - 2.f*c0.z;
            float a1x = n0.w + p0.w - 2.f*c0.w, a1y = n1.x + p1.x - 2.f*c1.x, a1z = n1.y + p1.y - 2.f*c1.y;
            float a2x = n1.z + p1.z - 2.f*c1.z, a2y = n1.w + p1.w - 2.f*c1.w, a2z = n2.x + p2.x - 2.f*c2.x;
            float a3x = n2.y + p2.y - 2.f*c2.y, a3y = n2.z + p2.z - 2.f*c2.z, a3z = n2.w + p2.w - 2.f*c2.w;

            float s0 = a0x*a0x + a0y*a0y + a0z*a0z;
            float s1 = a1x*a1x + a1y*a1y + a1z*a1z;
            float s2 = a2x*a2x + a2y*a2y + a2z*a2z;
            float s3 = a3x*a3x + a3y*a3y + a3z*a3z;

            float inert = 0.5f * (m4.x*s0 + m4.y*s1 + m4.z*s2 + m4.w*s3);
            float grav  = m4.x*c0.y + m4.y*c1.x + m4.z*c1.w + m4.w*c2.z;
            vertf = inert * (W_INERTIA / 3.0f) - grav * (W_GRAVITY * GRAVITY_C);
        } else {
            int t = c - nChunk;
            if (t < (V & 3)) {
                int v = (V & ~3) + t;
                float m  = mass[v];
                float ax = pos_next[3*v+0] + pos_prev[3*v+0] - 2.f*pos_curr[3*v+0];
                float ay = pos_next[3*v+1] + pos_prev[3*v+1] - 2.f*pos_curr[3*v+1];
                float az = pos_next[3*v+2] + pos_prev[3*v+2] - 2.f*pos_curr[3*v+2];
                float cy = pos_curr[3*v+1];
                vertf = 0.5f*m*(ax*ax+ay*ay+az*az) * (W_INERTIA / 3.0f)
                      - m*cy * (W_GRAVITY * GRAVITY_C);
            }
        }
        local = (double)vertf * (1.0 / (double)V);
    } else {
        // ---------- element block: Neo-Hookean strain ----------
        __shared__ float sR[EPB * 9];   // 18 KB

        const int blockBase = blockIdx.x * EPB;
        const int eA = blockBase + threadIdx.x;
        const int eB = blockBase + EBLK + threadIdx.x;
        const bool hasA = (eA < E);
        const bool hasB = (eB < E);

        // phase 1 (overlaps primary): streamed prefetch + smem staging
        const int4* __restrict__ elem4 = reinterpret_cast<const int4*>(elements);
        int4 idxA = hasA ? elem4[eA] : make_int4(0,0,0,0);
        int4 idxB = hasB ? elem4[eB] : make_int4(0,0,0,0);
        float volA = hasA ? rest_volumes[eA] : 0.0f;
        float volB = hasB ? rest_volumes[eB] : 0.0f;

        {
            const int nElem = min(EPB, E - blockBase);
            const int nFloats = nElem * 9;
            const float* Rg = rest_inv + (size_t)blockBase * 9;
            const int nVec = nFloats >> 2;
            const float4* Rg4 = reinterpret_cast<const float4*>(Rg);
            float4* sR4 = reinterpret_cast<float4*>(sR);
            for (int i = threadIdx.x; i < nVec; i += EBLK)
                sR4[i] = Rg4[i];
            for (int i = (nVec << 2) + threadIdx.x; i < nFloats; i += EBLK)
                sR[i] = Rg[i];
        }
        __syncthreads();

        // wait for pack (g_pos4 ready)
        asm volatile("griddepcontrol.wait;" ::: "memory");

        // phase 2: L2-only gathers
        float4 a0, a1, a2, a3, b0, b1, b2, b3;
        if (hasA) { a0 = ldcg_f4(&g_pos4[idxA.x]); a1 = ldcg_f4(&g_pos4[idxA.y]);
                    a2 = ldcg_f4(&g_pos4[idxA.z]); a3 = ldcg_f4(&g_pos4[idxA.w]); }
        if (hasB) { b0 = ldcg_f4(&g_pos4[idxB.x]); b1 = ldcg_f4(&g_pos4[idxB.y]);
                    b2 = ldcg_f4(&g_pos4[idxB.z]); b3 = ldcg_f4(&g_pos4[idxB.w]); }

        const float lam = lam_p[0];
        const float mu  = mu_p[0];

        float strain = 0.0f;
        if (hasA) strain += elem_energy4(a0, a1, a2, a3, sR + threadIdx.x * 9, volA, lam, mu);
        if (hasB) strain += elem_energy4(b0, b1, b2, b3, sR + (EBLK + threadIdx.x) * 9, volB, lam, mu);

        local = (double)strain * (W_STRAIN / (double)E);
    }

    // ---- reduce + completion epilogue ----
    double bsum = block_reduce(local);
    if (threadIdx.x == 0) {
        atomicAdd(&g_acc, bsum);
        __threadfence();
        unsigned int prev = atomicInc(&g_count, gridDim.x - 1);
        if (prev == gridDim.x - 1) {
            __threadfence();
            double total = atomicAdd(&g_acc, 0.0);
            out[0] = (float)total;
            g_acc = 0.0;   // reset for next graph replay
            __threadfence();
        }
    }
}

extern "C" void kernel_launch(void* const* d_in, const int* in_sizes, int n_in,
                              void* d_out, int out_size) {
    const float* pos_next = (const float*)d_in[0];
    const float* pos_curr = (const float*)d_in[1];
    const float* pos_prev = (const float*)d_in[2];
    const float* mass     = (const float*)d_in[3];
    const int*   elements = (const int*)d_in[4];
    const float* rest_vol = (const float*)d_in[5];
    const float* rest_inv = (const float*)d_in[6];
    const float* lam      = (const float*)d_in[7];
    const float* mu       = (const float*)d_in[8];
    float* out = (float*)d_out;

    const int V = in_sizes[0] / 3;
    const int E = in_sizes[5];

    // primary: pure pack
    {
        int work = (V >> 2) + 4;
        int blocks = (work + 255) / 256;
        pack_kernel<<<blocks, 256>>>(pos_next, V);
    }

    // secondary (PDL): element blocks + vertex tail blocks
    {
        int nEBlocks = (E + EPB - 1) / EPB;
        int nVBlocks = ((V >> 2) + 4 + EBLK - 1) / EBLK;
        int blocks = nEBlocks + nVBlocks;

        cudaLaunchConfig_t cfg = {};
        cfg.gridDim  = dim3((unsigned)blocks, 1, 1);
        cfg.blockDim = dim3(EBLK, 1, 1);
        cudaLaunchAttribute attrs[1];
        attrs[0].id = cudaLaunchAttributeProgrammaticStreamSerialization;
        attrs[0].val.programmaticStreamSerializationAllowed = 1;
        cfg.attrs = attrs;
        cfg.numAttrs = 1;
        cudaLaunchKernelEx(&cfg, main_kernel,
                           pos_next, pos_curr, pos_prev, mass,
                           elements, rest_vol, rest_inv, lam, mu,
                           V, E, nEBlocks, out);
    }
}